// round 5
// baseline (speedup 1.0000x reference)
#include <cuda_runtime.h>

// WavePool3D: 3D Haar wavelet pooling, kernel=stride=2.
// Input  x: [1, 32, 128, 128, 128] fp32 (W contiguous)
// Output  : [8, 1, 32, 64, 64, 64] fp32 (8 subbands LLL..HHH, contiguous)
//
// v4: smem-staged stores for long write bursts. Compute phase = v1
// (thread owns one (hl, wq): 4x LDG.128, 3-axis butterfly), results staged
// in a 16KB smem tile [8 subbands][8 h][64 w]. Store phase: warp f streams
// subband f as ONE 2KB contiguous burst (4x STG.128 per lane). Read side
// unchanged; write bursts per stream grow 256B -> 2KB.

#define C_DIM   32
#define DO_DIM  64
#define HO_DIM  64
#define H_PER_BLK 8

#define IN_W    128
#define IN_HW   (128 * 128)
#define IN_DHW  (128 * 128 * 128)

#define OUT_W   64
#define OUT_HW  (64 * 64)
#define OUT_DHW (64 * 64 * 64)
#define OUT_CDHW (C_DIM * OUT_DHW)   // stride between subbands

__global__ __launch_bounds__(256)
void wavepool3d_kernel(const float* __restrict__ x, float* __restrict__ out)
{
    __shared__ float tile[8 * H_PER_BLK * OUT_W];   // [f][hl][w] = 16KB

    // Block: [c:5][d:6][h3:3] ; thread: [hl:3][wq:5]
    unsigned bid = blockIdx.x;
    unsigned h3 = bid & 7u;
    unsigned d  = (bid >> 3) & 63u;
    unsigned c  = bid >> 9;

    unsigned tid = threadIdx.x;
    unsigned wq = tid & 31u;
    unsigned hl = tid >> 5;           // 0..7 (warp id in compute phase)
    unsigned h  = h3 * H_PER_BLK + hl;

    // ---- compute phase (identical math to v1) ----
    const float* base = x + (size_t)c * IN_DHW
                          + (size_t)(2u * d) * IN_HW
                          + (size_t)(2u * h) * IN_W
                          + 4u * wq;

    float4 a00 = __ldcs(reinterpret_cast<const float4*>(base));
    float4 a01 = __ldcs(reinterpret_cast<const float4*>(base + IN_W));
    float4 a10 = __ldcs(reinterpret_cast<const float4*>(base + IN_HW));
    float4 a11 = __ldcs(reinterpret_cast<const float4*>(base + IN_HW + IN_W));

    const float scale = 0.35355339059327378f;  // 1/(2*sqrt(2))

    float2 r[8];

    #pragma unroll
    for (int p = 0; p < 2; p++) {
        float s00_0 = p ? a00.z : a00.x, s00_1 = p ? a00.w : a00.y;
        float s01_0 = p ? a01.z : a01.x, s01_1 = p ? a01.w : a01.y;
        float s10_0 = p ? a10.z : a10.x, s10_1 = p ? a10.w : a10.y;
        float s11_0 = p ? a11.z : a11.x, s11_1 = p ? a11.w : a11.y;

        // k-axis (W)
        float e00 = s00_0 + s00_1, o00 = s00_1 - s00_0;
        float e01 = s01_0 + s01_1, o01 = s01_1 - s01_0;
        float e10 = s10_0 + s10_1, o10 = s10_1 - s10_0;
        float e11 = s11_0 + s11_1, o11 = s11_1 - s11_0;
        // j-axis (H)
        float le0 = e00 + e01, he0 = e01 - e00;
        float le1 = e10 + e11, he1 = e11 - e10;
        float lo0 = o00 + o01, ho0 = o01 - o00;
        float lo1 = o10 + o11, ho1 = o11 - o10;
        // i-axis (D)
        float f0 = (le0 + le1) * scale;   // LLL
        float f1 = (lo0 + lo1) * scale;   // LLH
        float f2 = (he0 + he1) * scale;   // LHL
        float f3 = (ho0 + ho1) * scale;   // LHH
        float f4 = (le1 - le0) * scale;   // HLL
        float f5 = (lo1 - lo0) * scale;   // HLH
        float f6 = (he1 - he0) * scale;   // HHL
        float f7 = (ho1 - ho0) * scale;   // HHH

        if (p == 0) {
            r[0].x = f0; r[1].x = f1; r[2].x = f2; r[3].x = f3;
            r[4].x = f4; r[5].x = f5; r[6].x = f6; r[7].x = f7;
        } else {
            r[0].y = f0; r[1].y = f1; r[2].y = f2; r[3].y = f3;
            r[4].y = f4; r[5].y = f5; r[6].y = f6; r[7].y = f7;
        }
    }

    // Stage to smem: [f][hl][2*wq .. 2*wq+1]. 32 lanes x 8B = 256B span,
    // conflict-free STS.64.
    #pragma unroll
    for (int f = 0; f < 8; f++) {
        *reinterpret_cast<float2*>(
            &tile[(unsigned)f * (H_PER_BLK * OUT_W) + hl * OUT_W + 2u * wq]) = r[f];
    }

    __syncthreads();

    // ---- store phase: warp f streams subband f as one 2KB burst ----
    // Output rows h3*8 .. h3*8+7 x 64 w are 512 CONSECUTIVE floats.
    unsigned f    = tid >> 5;        // warp id = subband
    unsigned lane = tid & 31u;

    const float* src = &tile[f * (H_PER_BLK * OUT_W)];
    float* dst = out + (size_t)f * OUT_CDHW
                     + (size_t)c * OUT_DHW
                     + (size_t)d * OUT_HW
                     + (size_t)(h3 * H_PER_BLK) * OUT_W;

    #pragma unroll
    for (int i = 0; i < 4; i++) {
        unsigned off = i * 128u + lane * 4u;   // float4 elements
        float4 v = *reinterpret_cast<const float4*>(src + off);
        __stcs(reinterpret_cast<float4*>(dst + off), v);
    }
}

extern "C" void kernel_launch(void* const* d_in, const int* in_sizes, int n_in,
                              void* d_out, int out_size)
{
    const float* x = (const float*)d_in[0];
    float* out = (float*)d_out;

    // grid = 32 * 64 * 8 = 16384 blocks, 256 threads each
    const unsigned grid = C_DIM * DO_DIM * (HO_DIM / H_PER_BLK);
    wavepool3d_kernel<<<grid, 256>>>(x, out);
}